// round 9
// baseline (speedup 1.0000x reference)
#include <cuda_runtime.h>

// Problem shape (fixed for this dataset)
#define N_NODES 400000
#define K_DOWN  5
#define NCONTRIB (N_NODES * K_DOWN)   // 2,000,000
#define F_DIM   128
#define NUP     100000
#define CAP     40                    // bucket capacity per destination
#define JMAX    8                     // fast-path unroll (P(c<=8) ~ 93%)

// Scratch (allocation-free rule: __device__ globals)
// entry = (w:f32 << 32) | src:u32 ; 400k * 40 * 8B = 128 MB
__device__ unsigned long long g_ent[(size_t)N_NODES * CAP];
__device__ int                g_cnt[N_NODES];

// ---------------------------------------------------------------------------
// K0: zero per-destination counters (1.6 MB)
__global__ void k_clear_cnt() {
    int i = blockIdx.x * blockDim.x + threadIdx.x;
    const int n4 = N_NODES / 4;
    if (i < n4) ((int4*)g_cnt)[i] = make_int4(0, 0, 0, 0);
}

// K1: bucket fill — thread per (n,k) contribution.
__global__ void k_fill(const float* __restrict__ wdn,
                       const int*   __restrict__ nidx) {
    int t = blockIdx.x * blockDim.x + threadIdx.x;
    if (t >= NCONTRIB) return;
    int dst = nidx[t];
    if (dst < 0 || dst >= N_NODES) return;
    float w  = wdn[t];
    int src  = t / K_DOWN;
    int pos  = atomicAdd(&g_cnt[dst], 1);
    if (pos < CAP) {
        unsigned long long e =
            ((unsigned long long)__float_as_uint(w) << 32) | (unsigned int)src;
        g_ent[(size_t)dst * CAP + pos] = e;
    }
}

// K2: fused gather + normalize — warp per output row.
// Fast path: fully unrolled 8-slot batch so all feature-row LDG.128s issue
// before any consumer -> MLP=8 instead of 1 (the round-5 version serialized
// one DRAM latency per contribution). Invalid slots read row 0 (L1-hot
// broadcast) with weight 0, keeping the load batch unpredicated and uniform.
__global__ void k_gather_fused(const int*   __restrict__ sel,
                               const float* __restrict__ feat,
                               float*       __restrict__ out) {
    int u = (blockIdx.x * blockDim.x + threadIdx.x) >> 5;
    if (u >= NUP) return;
    int lane = threadIdx.x & 31;

    int s = sel[u];
    float  wsum = 0.0f;
    float4 acc  = make_float4(0.f, 0.f, 0.f, 0.f);

    if (s >= 0 && s < N_NODES) {
        int c = g_cnt[s];
        if (c > CAP) c = CAP;
        const unsigned long long* bucket = g_ent + (size_t)s * CAP;
        const float4* feat4 = (const float4*)feat;

        // one coalesced fetch covers slots 0..31
        unsigned long long ev = (lane < c) ? bucket[lane] : 0ull;

        // ---- fast path: slots 0..7, compile-time unrolled ----
        int   srcj[JMAX];
        float wj  [JMAX];
        #pragma unroll
        for (int j = 0; j < JMAX; j++) {
            unsigned long long e = __shfl_sync(0xffffffffu, ev, j);
            bool v  = (j < c);
            srcj[j] = v ? (int)(unsigned int)(e & 0xffffffffull) : 0;
            wj[j]   = v ? __uint_as_float((unsigned int)(e >> 32)) : 0.0f;
        }
        float4 f[JMAX];
        #pragma unroll
        for (int j = 0; j < JMAX; j++) {
            f[j] = feat4[(size_t)srcj[j] * (F_DIM / 4) + lane];  // 8 independent LDG.128
        }
        #pragma unroll
        for (int j = 0; j < JMAX; j++) {
            wsum += wj[j];
            acc.x = fmaf(wj[j], f[j].x, acc.x);
            acc.y = fmaf(wj[j], f[j].y, acc.y);
            acc.z = fmaf(wj[j], f[j].z, acc.z);
            acc.w = fmaf(wj[j], f[j].w, acc.w);
        }

        // ---- rare tail: c > 8 (P ~ 7%) ----
        for (int j = JMAX; j < c; j++) {
            unsigned long long e;
            if (j < 32) e = __shfl_sync(0xffffffffu, ev, j);
            else        e = bucket[j];  // uniform broadcast load
            int   sj = (int)(unsigned int)(e & 0xffffffffull);
            float w  = __uint_as_float((unsigned int)(e >> 32));
            float4 ft = feat4[(size_t)sj * (F_DIM / 4) + lane];
            wsum += w;
            acc.x = fmaf(w, ft.x, acc.x);
            acc.y = fmaf(w, ft.y, acc.y);
            acc.z = fmaf(w, ft.z, acc.z);
            acc.w = fmaf(w, ft.w, acc.w);
        }
    }

    // relu(wsum) then fallback to 0.001 when <= 0
    float ws  = (wsum > 0.0f) ? wsum : 0.001f;
    float inv = 1.0f / ws;
    float4 o  = make_float4(acc.x * inv, acc.y * inv, acc.z * inv, acc.w * inv);
    ((float4*)(out + (size_t)u * F_DIM))[lane] = o;
}

// ---------------------------------------------------------------------------
extern "C" void kernel_launch(void* const* d_in, const int* in_sizes, int n_in,
                              void* d_out, int out_size) {
    const float* feat = (const float*)d_in[0];   // (N, 128) f32
    const float* wdn  = (const float*)d_in[1];   // (N, 5)   f32
    const int*   nidx = (const int*)  d_in[2];   // (N, 5)   i32
    const int*   sel  = (const int*)  d_in[3];   // (NUP, 1) i32
    float* out = (float*)d_out;                  // (NUP, 128) f32

    const int TPB = 256;

    // K0: zero counters
    {
        int n4 = N_NODES / 4;
        k_clear_cnt<<<(n4 + TPB - 1) / TPB, TPB>>>();
    }
    // K1: bucket fill (thread per contribution)
    k_fill<<<(NCONTRIB + TPB - 1) / TPB, TPB>>>(wdn, nidx);

    // K2: fused gather + normalize (warp per output row)
    {
        long long thr = (long long)NUP * 32;
        k_gather_fused<<<(int)((thr + TPB - 1) / TPB), TPB>>>(sel, feat, out);
    }
}

// round 11
// speedup vs baseline: 1.2819x; 1.2819x over previous
#include <cuda_runtime.h>

// Problem shape (fixed for this dataset)
#define N_NODES 400000
#define K_DOWN  5
#define NCONTRIB (N_NODES * K_DOWN)   // 2,000,000
#define F_DIM   128
#define NUP     100000
#define CAP     32                    // bucket capacity per destination
#define UNSEL   (-2147483647 - 1)     // INT_MIN: counter value for unselected rows

// Scratch (allocation-free rule: __device__ globals)
// entry = (w:f32 << 32) | src:u32 ; 400k * 32 * 8B = 102.4 MB
__device__ unsigned long long g_ent[(size_t)N_NODES * CAP];
__device__ int                g_cnt[N_NODES];

// ---------------------------------------------------------------------------
// K0: reset counters to INT_MIN ("not selected"). 1.6 MB of int4 stores.
__global__ void k_clear_cnt() {
    int i = blockIdx.x * blockDim.x + threadIdx.x;
    const int n4 = N_NODES / 4;
    if (i < n4) ((int4*)g_cnt)[i] = make_int4(UNSEL, UNSEL, UNSEL, UNSEL);
}

// K1: mark selected destinations: counter -> 0. Duplicate writes benign.
__global__ void k_mark(const int* __restrict__ sel) {
    int t = blockIdx.x * blockDim.x + threadIdx.x;
    if (t >= NUP) return;
    int s = sel[t];
    if (s >= 0 && s < N_NODES) g_cnt[s] = 0;
}

// K2: bucket fill — thread per (n,k) contribution. ONE atomic per
// contribution; the returned slot is >= 0 only for selected destinations
// (unselected counters start at INT_MIN and can never climb to 0), so
// ~78% of the scattered 8B bucket stores are skipped entirely.
__global__ void k_fill(const float* __restrict__ wdn,
                       const int*   __restrict__ nidx) {
    int t = blockIdx.x * blockDim.x + threadIdx.x;
    if (t >= NCONTRIB) return;
    int dst = nidx[t];
    if (dst < 0 || dst >= N_NODES) return;
    int pos = atomicAdd(&g_cnt[dst], 1);
    if (pos >= 0 && pos < CAP) {
        float w  = wdn[t];
        int src  = t / K_DOWN;
        unsigned long long e =
            ((unsigned long long)__float_as_uint(w) << 32) | (unsigned int)src;
        g_ent[(size_t)dst * CAP + pos] = e;
    }
}

// K3: fused gather + normalize — warp per output row (round-5 proven form:
// runtime loop with unroll 4 -> MLP~4 without register spills).
__global__ void k_gather_fused(const int*   __restrict__ sel,
                               const float* __restrict__ feat,
                               float*       __restrict__ out) {
    int u = (blockIdx.x * blockDim.x + threadIdx.x) >> 5;
    if (u >= NUP) return;
    int lane = threadIdx.x & 31;

    int s = sel[u];
    float  wsum = 0.0f;
    float4 acc  = make_float4(0.f, 0.f, 0.f, 0.f);

    if (s >= 0 && s < N_NODES) {
        int c = g_cnt[s];          // >= 0: every sel row was marked
        if (c < 0)   c = 0;
        if (c > CAP) c = CAP;
        const unsigned long long* bucket = g_ent + (size_t)s * CAP;
        const float4* feat4 = (const float4*)feat;

        // one coalesced fetch covers all slots (CAP == warp size)
        unsigned long long ev = (lane < c) ? bucket[lane] : 0ull;

        #pragma unroll 4
        for (int j = 0; j < c; j++) {
            unsigned long long e = __shfl_sync(0xffffffffu, ev, j);
            int   src = (int)(unsigned int)(e & 0xffffffffull);
            float w   = __uint_as_float((unsigned int)(e >> 32));
            float4 f  = feat4[(size_t)src * (F_DIM / 4) + lane];
            wsum += w;
            acc.x = fmaf(w, f.x, acc.x);
            acc.y = fmaf(w, f.y, acc.y);
            acc.z = fmaf(w, f.z, acc.z);
            acc.w = fmaf(w, f.w, acc.w);
        }
    }

    // relu(wsum) then fallback to 0.001 when <= 0
    float ws  = (wsum > 0.0f) ? wsum : 0.001f;
    float inv = 1.0f / ws;
    float4 o  = make_float4(acc.x * inv, acc.y * inv, acc.z * inv, acc.w * inv);
    ((float4*)(out + (size_t)u * F_DIM))[lane] = o;
}

// ---------------------------------------------------------------------------
extern "C" void kernel_launch(void* const* d_in, const int* in_sizes, int n_in,
                              void* d_out, int out_size) {
    const float* feat = (const float*)d_in[0];   // (N, 128) f32
    const float* wdn  = (const float*)d_in[1];   // (N, 5)   f32
    const int*   nidx = (const int*)  d_in[2];   // (N, 5)   i32
    const int*   sel  = (const int*)  d_in[3];   // (NUP, 1) i32
    float* out = (float*)d_out;                  // (NUP, 128) f32

    const int TPB = 256;

    // K0: reset counters to "unselected"
    {
        int n4 = N_NODES / 4;
        k_clear_cnt<<<(n4 + TPB - 1) / TPB, TPB>>>();
    }
    // K1: mark selected destinations
    k_mark<<<(NUP + TPB - 1) / TPB, TPB>>>(sel);

    // K2: bucket fill (thread per contribution, selected dsts only)
    k_fill<<<(NCONTRIB + TPB - 1) / TPB, TPB>>>(wdn, nidx);

    // K3: fused gather + normalize (warp per output row)
    {
        long long thr = (long long)NUP * 32;
        k_gather_fused<<<(int)((thr + TPB - 1) / TPB), TPB>>>(sel, feat, out);
    }
}

// round 12
// speedup vs baseline: 1.3398x; 1.0452x over previous
#include <cuda_runtime.h>

// Problem shape (fixed for this dataset)
#define N_NODES 400000
#define K_DOWN  5
#define NCONTRIB (N_NODES * K_DOWN)   // 2,000,000
#define F_DIM   128
#define NUP     100000
#define CAP     32                    // bucket capacity per destination
#define UNSEL   (-2147483647 - 1)     // INT_MIN: counter value for unselected rows

// Scratch (allocation-free rule: __device__ globals)
// entry = (w:f32 << 32) | src:u32 ; 400k * 32 * 8B = 102.4 MB
__device__ unsigned long long g_ent[(size_t)N_NODES * CAP];
__device__ int                g_cnt[N_NODES];

// ---------------------------------------------------------------------------
// K0: reset counters to INT_MIN ("not selected"). 1.6 MB of int4 stores.
__global__ void k_clear_cnt() {
    int i = blockIdx.x * blockDim.x + threadIdx.x;
    const int n4 = N_NODES / 4;
    if (i < n4) ((int4*)g_cnt)[i] = make_int4(UNSEL, UNSEL, UNSEL, UNSEL);
}

// K1: mark selected destinations: counter -> 0. Duplicate writes benign.
__global__ void k_mark(const int* __restrict__ sel) {
    int t = blockIdx.x * blockDim.x + threadIdx.x;
    if (t >= NUP) return;
    int s = sel[t];
    if (s >= 0 && s < N_NODES) g_cnt[s] = 0;
}

// K2: bucket fill — thread per (n,k) contribution. ONE atomic per
// contribution; the returned slot is >= 0 only for selected destinations
// (unselected counters start at INT_MIN and can never climb to 0), so
// ~78% of the scattered 8B bucket stores are skipped entirely.
__global__ void k_fill(const float* __restrict__ wdn,
                       const int*   __restrict__ nidx) {
    int t = blockIdx.x * blockDim.x + threadIdx.x;
    if (t >= NCONTRIB) return;
    int dst = nidx[t];
    if (dst < 0 || dst >= N_NODES) return;
    int pos = atomicAdd(&g_cnt[dst], 1);
    if (pos >= 0 && pos < CAP) {
        float w  = wdn[t];
        int src  = t / K_DOWN;
        unsigned long long e =
            ((unsigned long long)__float_as_uint(w) << 32) | (unsigned int)src;
        g_ent[(size_t)dst * CAP + pos] = e;
    }
}

// K3: fused gather + normalize — warp per output row.
// Latency-chain fix vs round 9: the bucket load no longer depends on the
// counter load (they issue concurrently -> 3 serial DRAM trips, not 4).
// Only lanes 0..15 read the bucket (c > 16 has P ~ 4e-6; rare warp-uniform
// second load covers it), halving bucket traffic. __ldcs/__stcs keep
// read-once/write-once streams from evicting the feature working set in L2.
__global__ void k_gather_fused(const int*   __restrict__ sel,
                               const float* __restrict__ feat,
                               float*       __restrict__ out) {
    int u = (blockIdx.x * blockDim.x + threadIdx.x) >> 5;
    if (u >= NUP) return;
    int lane = threadIdx.x & 31;

    int s = sel[u];
    float  wsum = 0.0f;
    float4 acc  = make_float4(0.f, 0.f, 0.f, 0.f);

    if (s >= 0 && s < N_NODES) {
        const unsigned long long* bucket = g_ent + (size_t)s * CAP;

        // two INDEPENDENT loads — one shared memory round-trip
        int c = g_cnt[s];
        unsigned long long ev = (lane < 16) ? __ldcs(bucket + lane) : 0ull;

        if (c < 0)   c = 0;
        if (c > CAP) c = CAP;
        if (c > 16) {                       // warp-uniform, P ~ 4e-6
            if (lane >= 16) ev = __ldcs(bucket + lane);
        }

        const float4* feat4 = (const float4*)feat;
        #pragma unroll 4
        for (int j = 0; j < c; j++) {
            unsigned long long e = __shfl_sync(0xffffffffu, ev, j);
            int   src = (int)(unsigned int)(e & 0xffffffffull);
            float w   = __uint_as_float((unsigned int)(e >> 32));
            float4 f  = feat4[(size_t)src * (F_DIM / 4) + lane];
            wsum += w;
            acc.x = fmaf(w, f.x, acc.x);
            acc.y = fmaf(w, f.y, acc.y);
            acc.z = fmaf(w, f.z, acc.z);
            acc.w = fmaf(w, f.w, acc.w);
        }
    }

    // relu(wsum) then fallback to 0.001 when <= 0
    float ws  = (wsum > 0.0f) ? wsum : 0.001f;
    float inv = 1.0f / ws;
    float4 o  = make_float4(acc.x * inv, acc.y * inv, acc.z * inv, acc.w * inv);
    __stcs((float4*)(out + (size_t)u * F_DIM) + lane, o);
}

// ---------------------------------------------------------------------------
extern "C" void kernel_launch(void* const* d_in, const int* in_sizes, int n_in,
                              void* d_out, int out_size) {
    const float* feat = (const float*)d_in[0];   // (N, 128) f32
    const float* wdn  = (const float*)d_in[1];   // (N, 5)   f32
    const int*   nidx = (const int*)  d_in[2];   // (N, 5)   i32
    const int*   sel  = (const int*)  d_in[3];   // (NUP, 1) i32
    float* out = (float*)d_out;                  // (NUP, 128) f32

    const int TPB = 256;

    // K0: reset counters to "unselected"
    {
        int n4 = N_NODES / 4;
        k_clear_cnt<<<(n4 + TPB - 1) / TPB, TPB>>>();
    }
    // K1: mark selected destinations
    k_mark<<<(NUP + TPB - 1) / TPB, TPB>>>(sel);

    // K2: bucket fill (thread per contribution, selected dsts only)
    k_fill<<<(NCONTRIB + TPB - 1) / TPB, TPB>>>(wdn, nidx);

    // K3: fused gather + normalize (warp per output row)
    {
        long long thr = (long long)NUP * 32;
        k_gather_fused<<<(int)((thr + TPB - 1) / TPB), TPB>>>(sel, feat, out);
    }
}

// round 13
// speedup vs baseline: 1.4811x; 1.1054x over previous
#include <cuda_runtime.h>

// Problem shape (fixed for this dataset)
#define N_NODES 400000
#define K_DOWN  5
#define NCONTRIB (N_NODES * K_DOWN)   // 2,000,000
#define F_DIM   128
#define NUP     100000
#define CAP     32                    // bucket capacity per destination
#define UNSEL   (-2147483647 - 1)     // INT_MIN: counter value for unselected rows
#define UPW     4                     // outputs per warp in the gather

// Scratch (allocation-free rule: __device__ globals)
// entry = (w:f32 << 32) | src:u32 ; 400k * 32 * 8B = 102.4 MB
__device__ unsigned long long g_ent[(size_t)N_NODES * CAP];
__device__ int                g_cnt[N_NODES];

// ---------------------------------------------------------------------------
// K0: reset counters to INT_MIN ("not selected"). 1.6 MB of int4 stores.
__global__ void k_clear_cnt() {
    int i = blockIdx.x * blockDim.x + threadIdx.x;
    const int n4 = N_NODES / 4;
    if (i < n4) ((int4*)g_cnt)[i] = make_int4(UNSEL, UNSEL, UNSEL, UNSEL);
}

// K1: mark selected destinations: counter -> 0. Duplicate writes benign.
__global__ void k_mark(const int* __restrict__ sel) {
    int t = blockIdx.x * blockDim.x + threadIdx.x;
    if (t >= NUP) return;
    int s = sel[t];
    if (s >= 0 && s < N_NODES) g_cnt[s] = 0;
}

// K2: bucket fill — thread per (n,k) contribution. ONE atomic per
// contribution; slot >= 0 only for selected destinations, so ~78% of the
// scattered bucket stores are skipped.
__global__ void k_fill(const float* __restrict__ wdn,
                       const int*   __restrict__ nidx) {
    int t = blockIdx.x * blockDim.x + threadIdx.x;
    if (t >= NCONTRIB) return;
    int dst = nidx[t];
    if (dst < 0 || dst >= N_NODES) return;
    int pos = atomicAdd(&g_cnt[dst], 1);
    if (pos >= 0 && pos < CAP) {
        float w  = wdn[t];
        int src  = t / K_DOWN;
        unsigned long long e =
            ((unsigned long long)__float_as_uint(w) << 32) | (unsigned int)src;
        g_ent[(size_t)dst * CAP + pos] = e;
    }
}

// K3: fused gather + normalize — FOUR output rows per warp.
//  * one 64-bit load/lane covers slots 0..7 of all four buckets
//    (lane = i*8 + slot): full lane utilization, one chain shared by 4 rows
//  * feature loop unrolled j=0..7 with the 4 outputs interleaved per step:
//    4 independent LDG.128 per j, only acc carries across steps -> high MLP
//  * dead slots (j >= c_i) read row 0 (L1-hot) with weight 0
//  * rare tail c > 8 handled serially per output
__global__ void k_gather_fused(const int*   __restrict__ sel,
                               const float* __restrict__ feat,
                               float*       __restrict__ out) {
    int warp = (blockIdx.x * blockDim.x + threadIdx.x) >> 5;
    int u0 = warp * UPW;
    if (u0 >= NUP) return;
    int lane = threadIdx.x & 31;
    int grp  = lane >> 3;          // which of the 4 outputs this lane serves
    int slot = lane & 7;           // bucket slot 0..7

    // uniform scalar loads: all lanes hold all four (s, c)
    int s[UPW], c[UPW];
    #pragma unroll
    for (int i = 0; i < UPW; i++) {
        int u = u0 + i;
        int sv = (u < NUP) ? sel[u] : -1;
        s[i] = (sv >= 0 && sv < N_NODES) ? sv : -1;
    }
    #pragma unroll
    for (int i = 0; i < UPW; i++) {
        int cv = (s[i] >= 0) ? g_cnt[s[i]] : 0;
        if (cv < 0)   cv = 0;
        if (cv > CAP) cv = CAP;
        c[i] = cv;
    }

    // one coalesced trip: slots 0..7 of all four buckets
    int sg = s[grp];
    unsigned long long ev = (sg >= 0)
        ? __ldcs(g_ent + (size_t)sg * CAP + slot) : 0ull;

    const float4* feat4 = (const float4*)feat;
    float  wsum[UPW];
    float4 acc [UPW];
    #pragma unroll
    for (int i = 0; i < UPW; i++) {
        wsum[i] = 0.0f;
        acc[i]  = make_float4(0.f, 0.f, 0.f, 0.f);
    }

    #pragma unroll
    for (int j = 0; j < 8; j++) {
        float  wj[UPW];
        float4 f [UPW];
        #pragma unroll
        for (int i = 0; i < UPW; i++) {
            unsigned long long e = __shfl_sync(0xffffffffu, ev, i * 8 + j);
            bool v  = (j < c[i]);
            int  sj = v ? (int)(unsigned int)(e & 0xffffffffull) : 0;
            wj[i]   = v ? __uint_as_float((unsigned int)(e >> 32)) : 0.0f;
            f[i]    = feat4[(size_t)sj * (F_DIM / 4) + lane];
        }
        #pragma unroll
        for (int i = 0; i < UPW; i++) {
            wsum[i] += wj[i];
            acc[i].x = fmaf(wj[i], f[i].x, acc[i].x);
            acc[i].y = fmaf(wj[i], f[i].y, acc[i].y);
            acc[i].z = fmaf(wj[i], f[i].z, acc[i].z);
            acc[i].w = fmaf(wj[i], f[i].w, acc[i].w);
        }
    }

    // rare tail: c > 8 (P ~ 7% per output)
    #pragma unroll
    for (int i = 0; i < UPW; i++) {
        if (c[i] > 8) {
            const unsigned long long* bucket = g_ent + (size_t)s[i] * CAP;
            for (int j = 8; j < c[i]; j++) {
                unsigned long long e = __ldcs(bucket + j);  // uniform broadcast
                int   sj = (int)(unsigned int)(e & 0xffffffffull);
                float w  = __uint_as_float((unsigned int)(e >> 32));
                float4 ft = feat4[(size_t)sj * (F_DIM / 4) + lane];
                wsum[i] += w;
                acc[i].x = fmaf(w, ft.x, acc[i].x);
                acc[i].y = fmaf(w, ft.y, acc[i].y);
                acc[i].z = fmaf(w, ft.z, acc[i].z);
                acc[i].w = fmaf(w, ft.w, acc[i].w);
            }
        }
    }

    // normalize + write
    #pragma unroll
    for (int i = 0; i < UPW; i++) {
        int u = u0 + i;
        if (u >= NUP) break;
        float ws  = (wsum[i] > 0.0f) ? wsum[i] : 0.001f;
        float inv = 1.0f / ws;
        float4 o  = make_float4(acc[i].x * inv, acc[i].y * inv,
                                acc[i].z * inv, acc[i].w * inv);
        __stcs((float4*)(out + (size_t)u * F_DIM) + lane, o);
    }
}

// ---------------------------------------------------------------------------
extern "C" void kernel_launch(void* const* d_in, const int* in_sizes, int n_in,
                              void* d_out, int out_size) {
    const float* feat = (const float*)d_in[0];   // (N, 128) f32
    const float* wdn  = (const float*)d_in[1];   // (N, 5)   f32
    const int*   nidx = (const int*)  d_in[2];   // (N, 5)   i32
    const int*   sel  = (const int*)  d_in[3];   // (NUP, 1) i32
    float* out = (float*)d_out;                  // (NUP, 128) f32

    const int TPB = 256;

    // K0: reset counters to "unselected"
    {
        int n4 = N_NODES / 4;
        k_clear_cnt<<<(n4 + TPB - 1) / TPB, TPB>>>();
    }
    // K1: mark selected destinations
    k_mark<<<(NUP + TPB - 1) / TPB, TPB>>>(sel);

    // K2: bucket fill (thread per contribution, selected dsts only)
    k_fill<<<(NCONTRIB + TPB - 1) / TPB, TPB>>>(wdn, nidx);

    // K3: fused gather + normalize (4 output rows per warp)
    {
        int warps  = (NUP + UPW - 1) / UPW;          // 25000
        long long thr = (long long)warps * 32;
        k_gather_fused<<<(int)((thr + TPB - 1) / TPB), TPB>>>(sel, feat, out);
    }
}